// round 11
// baseline (speedup 1.0000x reference)
#include <cuda_runtime.h>
#include <cuda_bf16.h>
#include <cstdint>

#define NV 16384
#define NE 16384
#define DIM 256
#define HW 1024
#define CHW 262144
#define OUT_ELEMS 4194304

#define BM 64
#define BN 64
#define NTILES (NE / BN)            // 256
#define TSTAGES (NTILES * 4)        // 1024 (BK=64 chunks)
#define STG_BYTES 24576             // 3 splits * 64 n * 128 B
#define SMEM_A_BYTES 98304          // 3 * 64 * 512
#define SMEM_TOTAL (SMEM_A_BYTES + 4 * STG_BYTES)  // 196608

__device__ float g_z2[NV];
__device__ int g_idx[NV];
__device__ float g_partial[512];
__device__ __align__(16) uint32_t g_cb3[3][NE * DIM / 2];  // [split][n*128 + kpair]

// ---------------------------------------------------------------------------
__device__ __forceinline__ uint32_t smem_u32(const void* p) {
    uint32_t a;
    asm("{ .reg .u64 t; cvta.to.shared.u64 t, %1; cvt.u32.u64 %0, t; }" : "=r"(a) : "l"(p));
    return a;
}

__device__ __forceinline__ void split3(float v, uint32_t& a, uint32_t& b, uint32_t& c) {
    __nv_bfloat16 h1 = __float2bfloat16(v);
    float r1 = v - __bfloat162float(h1);
    __nv_bfloat16 h2 = __float2bfloat16(r1);
    float r2 = r1 - __bfloat162float(h2);
    __nv_bfloat16 h3 = __float2bfloat16(r2);
    a = (uint32_t)__bfloat16_as_ushort(h1);
    b = (uint32_t)__bfloat16_as_ushort(h2);
    c = (uint32_t)__bfloat16_as_ushort(h3);
}

#define LDSM_X4(r, addr) \
    asm volatile("ldmatrix.sync.aligned.m8n8.x4.shared.b16 {%0,%1,%2,%3}, [%4];" \
        : "=r"((r)[0]), "=r"((r)[1]), "=r"((r)[2]), "=r"((r)[3]) : "r"(addr))

#define MMA16816(c, a, b0, b1) \
    asm volatile("mma.sync.aligned.m16n8k16.row.col.f32.bf16.bf16.f32 " \
        "{%0,%1,%2,%3}, {%4,%5,%6,%7}, {%8,%9}, {%0,%1,%2,%3};" \
        : "+f"((c)[0]), "+f"((c)[1]), "+f"((c)[2]), "+f"((c)[3]) \
        : "r"((a)[0]), "r"((a)[1]), "r"((a)[2]), "r"((a)[3]), "r"(b0), "r"(b1))

#define CP_COMMIT() asm volatile("cp.async.commit_group;" ::: "memory")
#define CP_WAIT(n) asm volatile("cp.async.wait_group %0;" :: "n"(n) : "memory")

// ---------------------------------------------------------------------------
// z2[m] = sum_c z[b,c,p]^2
// ---------------------------------------------------------------------------
__global__ __launch_bounds__(256) void z2_kernel(const float* __restrict__ z) {
    int m = blockIdx.x * 8 + (threadIdx.x >> 5);
    int lane = threadIdx.x & 31;
    int b = m >> 10, p = m & 1023;
    const float* base = z + (size_t)b * CHW + p;
    float s = 0.f;
#pragma unroll
    for (int c = 0; c < DIM; c += 32) {
        float v = base[(size_t)(c + lane) * HW];
        s = fmaf(v, v, s);
    }
#pragma unroll
    for (int o = 16; o > 0; o >>= 1) s += __shfl_xor_sync(0xffffffffu, s, o);
    if (lane == 0) g_z2[m] = s;
}

// ---------------------------------------------------------------------------
// Codebook 3-way bf16 split, packed bf16x2 per k-pair: g_cb3[s][n*128 + kk]
// ---------------------------------------------------------------------------
__global__ __launch_bounds__(256) void cbsplit_kernel(const float* __restrict__ cb) {
    int i = blockIdx.x * 256 + threadIdx.x;
    float2 v = ((const float2*)cb)[i];
    uint32_t a0, b0, c0, a1, b1, c1;
    split3(v.x, a0, b0, c0);
    split3(v.y, a1, b1, c1);
    g_cb3[0][i] = a0 | (a1 << 16);
    g_cb3[1][i] = b0 | (b1 << 16);
    g_cb3[2][i] = c0 | (c1 << 16);
}

// ---------------------------------------------------------------------------
// Producer: stage t = (ntile, kc) -> 24KB (3 splits x 64 n x 128 B) via cp.async
// ---------------------------------------------------------------------------
__device__ __forceinline__ void produce_stage(int t, uint32_t sB, int tid) {
    const int nt = t >> 2, kc = t & 3, slot = t & 3;
    const uint32_t stg = sB + slot * STG_BYTES;
    const char* gb = (const char*)g_cb3;
#pragma unroll
    for (int q = 0; q < 6; q++) {
        int cid = q * 256 + tid;
        int sp = cid >> 9, rem = cid & 511;
        int n = rem >> 3, kcol = rem & 7;
        const char* gp = gb + (size_t)sp * (NE * 512) + (size_t)(nt * 64 + n) * 512
                         + kc * 128 + kcol * 16;
        uint32_t soff = (uint32_t)((sp * 64 + n) * 128 + kcol * 16);
        uint32_t sa = stg + (soff ^ ((soff >> 3) & 0x70));
        asm volatile("cp.async.cg.shared.global [%0], [%1], 16;" :: "r"(sa), "l"(gp));
    }
    CP_COMMIT();
}

// ---------------------------------------------------------------------------
// Main kernel: fused split-bf16 mma.sync GEMM + argmin. 256 CTAs x 256 thr.
// ---------------------------------------------------------------------------
__global__ __launch_bounds__(256, 1) void vq_mma(const float* __restrict__ z) {
    extern __shared__ __align__(128) char smem[];
    const uint32_t sA = smem_u32(smem);
    const uint32_t sB = sA + SMEM_A_BYTES;
    const int tid = threadIdx.x;
    const int m0 = blockIdx.x * BM;

    // prologue: stages 0..2 in flight
    produce_stage(0, sB, tid);
    produce_stage(1, sB, tid);
    produce_stage(2, sB, tid);

    // ---- A init: 3-way split of 64 z-rows into smem (swizzled) ----
    {
        int ml = tid & 63, q = tid >> 6;
        int mg = m0 + ml, bb = mg >> 10, p = mg & 1023;
        const float* zr = z + (size_t)bb * CHW + p;
        uint32_t pat = (uint32_t)((ml & 7) << 4);
        char* ab = smem + ml * 512;
#pragma unroll 4
        for (int kk = 0; kk < 64; kk += 2) {
            int k = q * 64 + kk;
            float v0 = zr[(size_t)k * HW];
            float v1 = zr[(size_t)(k + 1) * HW];
            uint32_t a0, b0, c0, a1, b1, c1;
            split3(v0, a0, b0, c0);
            split3(v1, a1, b1, c1);
            uint32_t ad = ((uint32_t)(k * 2)) ^ pat;
            *(uint32_t*)(ab + ad)          = a0 | (a1 << 16);
            *(uint32_t*)(ab + 32768 + ad)  = b0 | (b1 << 16);
            *(uint32_t*)(ab + 65536 + ad)  = c0 | (c1 << 16);
        }
    }
    __syncthreads();

    const int wid = tid >> 5, lane = tid & 31;
    const int wm = wid & 1, wn = wid >> 1;   // 2(m) x 4(n) warp grid
    const int lr = lane & 15, lh = lane >> 4;

    float acc[2][2][4];
#pragma unroll
    for (int i = 0; i < 2; i++)
#pragma unroll
        for (int j = 0; j < 2; j++)
#pragma unroll
            for (int q = 0; q < 4; q++) acc[i][j][q] = 0.f;

    float bd[4];
    int bn[4];
    float myz2[4];
#pragma unroll
    for (int s = 0; s < 4; s++) {
        bd[s] = 3.4e38f;
        bn[s] = 0;
        int r = wm * 32 + (s >> 1) * 16 + (s & 1) * 8 + (lane >> 2);
        myz2[s] = g_z2[m0 + r];
    }

    static const int SI[6] = {0, 0, 1, 0, 1, 2};
    static const int SJ[6] = {0, 1, 0, 2, 1, 0};

    for (int t = 0; t < TSTAGES; t++) {
        if (t < TSTAGES - 2) CP_WAIT(2);
        else if (t == TSTAGES - 2) CP_WAIT(1);
        else CP_WAIT(0);
        __syncthreads();
        if (t + 3 < TSTAGES) produce_stage(t + 3, sB, tid);

        const int kc = t & 3;
        const uint32_t stg = sB + (t & 3) * STG_BYTES;

#pragma unroll
        for (int ks = 0; ks < 4; ks++) {
            uint32_t a[3][2][4];
#pragma unroll
            for (int si = 0; si < 3; si++)
#pragma unroll
                for (int mf = 0; mf < 2; mf++) {
                    int m = wm * 32 + mf * 16 + lr;
                    uint32_t kb = (uint32_t)(kc * 128 + ks * 32 + lh * 16);
                    uint32_t ad = sA + si * 32768 + m * 512 + (kb ^ ((uint32_t)(m & 7) << 4));
                    LDSM_X4(a[si][mf], ad);
                }
            uint32_t bq[3][4];
#pragma unroll
            for (int sj = 0; sj < 3; sj++) {
                int r = sj * 64 + wn * 16 + lr;
                uint32_t soff = (uint32_t)(r * 128 + ks * 32 + lh * 16);
                uint32_t ad = stg + (soff ^ ((soff >> 3) & 0x70));
                LDSM_X4(bq[sj], ad);
            }
#pragma unroll
            for (int pp = 0; pp < 6; pp++) {
                const int si = SI[pp], sj = SJ[pp];
#pragma unroll
                for (int mf = 0; mf < 2; mf++)
#pragma unroll
                    for (int nf = 0; nf < 2; nf++)
                        MMA16816(acc[mf][nf], a[si][mf], bq[sj][nf], bq[sj][nf + 2]);
            }
        }

        if (kc == 3) {
            // epilogue for n-tile (t>>2): d = fl(z2 - 2*dot), running argmin
            const int n0 = (t >> 2) * 64;
#pragma unroll
            for (int mf = 0; mf < 2; mf++)
#pragma unroll
                for (int rh = 0; rh < 2; rh++) {
                    const int s = mf * 2 + rh;
                    float zz = myz2[s];
                    float lbd = bd[s];
                    int lbn = bn[s];
#pragma unroll
                    for (int nf = 0; nf < 2; nf++)
#pragma unroll
                        for (int c = 0; c < 2; c++) {
                            float d = fmaf(-2.f, acc[mf][nf][rh * 2 + c], zz);
                            int n = n0 + wn * 16 + nf * 8 + (lane & 3) * 2 + c;
                            if (d < lbd) { lbd = d; lbn = n; }
                        }
                    bd[s] = lbd;
                    bn[s] = lbn;
                }
#pragma unroll
            for (int i = 0; i < 2; i++)
#pragma unroll
                for (int j = 0; j < 2; j++)
#pragma unroll
                    for (int q = 0; q < 4; q++) acc[i][j][q] = 0.f;
        }
    }

    // ---- cross-thread argmin reduce (lowest-n tie-break) ----
    __syncthreads();
    float* rD = (float*)(smem + SMEM_A_BYTES);
    int* rN = (int*)(smem + SMEM_A_BYTES + 1024);
#pragma unroll
    for (int s = 0; s < 4; s++) {
        float lbd = bd[s];
        int lbn = bn[s];
#pragma unroll
        for (int o = 1; o <= 2; o <<= 1) {
            float od = __shfl_xor_sync(0xffffffffu, lbd, o);
            int on = __shfl_xor_sync(0xffffffffu, lbn, o);
            if (od < lbd || (od == lbd && on < lbn)) { lbd = od; lbn = on; }
        }
        if ((lane & 3) == 0) {
            int r = wm * 32 + (s >> 1) * 16 + (s & 1) * 8 + (lane >> 2);
            rD[wn * 64 + r] = lbd;
            rN[wn * 64 + r] = lbn;
        }
    }
    __syncthreads();
    if (tid < 64) {
        float lbd = rD[tid];
        int lbn = rN[tid];
#pragma unroll
        for (int w = 1; w < 4; w++) {
            float od = rD[w * 64 + tid];
            int on = rN[w * 64 + tid];
            if (od < lbd || (od == lbd && on < lbn)) { lbd = od; lbn = on; }
        }
        g_idx[m0 + tid] = lbn;
    }
}

// ---------------------------------------------------------------------------
// Gather z_q, straight-through out fl(z + fl(zq - z)), loss partials, idx.
// ---------------------------------------------------------------------------
__global__ __launch_bounds__(256) void outloss_kernel(const float* __restrict__ z,
                                                      const float* __restrict__ cb,
                                                      float* __restrict__ dout) {
    __shared__ float s_zq[32][257];
    __shared__ int s_idx[32];
    __shared__ float s_red[8];
    const int tid = threadIdx.x;
    const int m0 = blockIdx.x * 32;
    const int b = m0 >> 10;
    const int p0 = m0 & 1023;

    if (tid < 32) s_idx[tid] = g_idx[m0 + tid];
    __syncthreads();

    const int w = tid >> 5, lane = tid & 31;
    for (int r = w; r < 32; r += 8) {
        const float* row = cb + (size_t)s_idx[r] * DIM;
        for (int c = lane; c < DIM; c += 32) s_zq[r][c] = row[c];
    }
    __syncthreads();

    const float* zb = z + (size_t)b * CHW + p0;
    float* ob = dout + (size_t)b * CHW + p0;
    float lsum = 0.f;
#pragma unroll 4
    for (int i = 0; i < 32; i++) {
        int c = i * 8 + w;
        float q = s_zq[lane][c];
        float zv = zb[(size_t)c * HW + lane];
        float t = q - zv;
        lsum = fmaf(t, t, lsum);
        ob[(size_t)c * HW + lane] = zv + t;
    }

    if (tid < 32) dout[OUT_ELEMS + 1 + m0 + tid] = (float)s_idx[tid];

#pragma unroll
    for (int o = 16; o > 0; o >>= 1) lsum += __shfl_xor_sync(0xffffffffu, lsum, o);
    if (lane == 0) s_red[w] = lsum;
    __syncthreads();
    if (tid == 0) {
        float t = 0.f;
#pragma unroll
        for (int k = 0; k < 8; k++) t += s_red[k];
        g_partial[blockIdx.x] = t;
    }
}

__global__ __launch_bounds__(256) void final_kernel(float* __restrict__ dout) {
    __shared__ float s_red[8];
    int tid = threadIdx.x;
    float s = g_partial[tid] + g_partial[tid + 256];
#pragma unroll
    for (int o = 16; o > 0; o >>= 1) s += __shfl_xor_sync(0xffffffffu, s, o);
    if ((tid & 31) == 0) s_red[tid >> 5] = s;
    __syncthreads();
    if (tid == 0) {
        float t = 0.f;
#pragma unroll
        for (int k = 0; k < 8; k++) t += s_red[k];
        float m = t / (float)OUT_ELEMS;
        dout[OUT_ELEMS] = m + 0.25f * m;
    }
}

extern "C" void kernel_launch(void* const* d_in, const int* in_sizes, int n_in,
                              void* d_out, int out_size) {
    const float* z = (const float*)d_in[0];
    const float* cb = (const float*)d_in[1];
    float* out = (float*)d_out;
    (void)in_sizes; (void)n_in; (void)out_size;

    cudaFuncSetAttribute(vq_mma, cudaFuncAttributeMaxDynamicSharedMemorySize, SMEM_TOTAL);

    z2_kernel<<<NV / 8, 256>>>(z);
    cbsplit_kernel<<<NE * DIM / 2 / 256, 256>>>(cb);
    vq_mma<<<NV / BM, 256, SMEM_TOTAL>>>(z);
    outloss_kernel<<<NV / 32, 256>>>(z, cb, out);
    final_kernel<<<1, 256>>>(out);
}